// round 15
// baseline (speedup 1.0000x reference)
#include <cuda_runtime.h>
#include <cstdint>

// D-FPS (B=8, N=32768, npoint=2048) + gather xyz -> out (B,3,2048) fp32.
//
// One 4-CTA cluster per batch (32 CTAs, 256 threads = 8 warps). Each thread
// owns 32 points, PACKED f32x2 in registers; running-min temp in registers.
// Smaller cluster than the 8-CTA variant: fewer barrier participants (less
// arrival skew), half the DSMEM fan-out, 4-slot winner pick.
// Per iteration:
//   - packed add/mul.rn.f32x2 distance update (per-lane .rn => bit-exact)
//   - warp argmax via redux.sync (float bits of v>=0 are u32-monotone),
//     min-index tie-break == jnp.argmax first-occurrence
//   - CTA argmax in warp0 via redux over 8 warp candidates; lanes 0..3 push
//     {key,x,y,z} to cluster CTA dst==lane in parallel (mapa +
//     st.shared::cluster); winner coords from CTA-local smem table (LDS)
//   - ONE barrier.cluster (arrive releases the remote stores, wait acquires)
//   - every thread picks the cluster winner from its own 4 smem slots.
// Slots double-buffered by parity: a same-parity overwrite for iter j+2 can
// only be issued after the cluster barrier of iter j+1, which post-dates all
// reads of the iter-j slots.

constexpr int BATCH   = 8;
constexpr int NPTS    = 32768;
constexpr int NPOINT  = 2048;
constexpr int CLUSTER = 4;
constexpr int T       = 256;
constexpr int PER_CTA = NPTS / CLUSTER;  // 8192
constexpr int P       = PER_CTA / T;     // 32 points / thread
constexpr int NPAIR   = P / 2;           // 16 packed pairs
constexpr int NW      = T / 32;          // 8 warps

__device__ __forceinline__ uint32_t smem_u32(const void* p) {
    uint32_t a;
    asm("{ .reg .u64 t; cvta.to.shared.u64 t, %1; cvt.u32.u64 %0, t; }"
        : "=r"(a) : "l"(p));
    return a;
}

extern __shared__ float s_dyn[];  // sx[8192] | sy[8192] | sz[8192] = 96KB

__global__ __launch_bounds__(T, 1) __cluster_dims__(CLUSTER, 1, 1)
void fps_cluster_kernel(const float* __restrict__ xyz_t, float* __restrict__ out)
{
    const int b = blockIdx.x >> 2;
    uint32_t rank;
    asm("mov.u32 %0, %%cluster_ctarank;" : "=r"(rank));

    const float* __restrict__ xs = xyz_t + (size_t)b * 3 * NPTS;
    const float* __restrict__ ys = xs + NPTS;
    const float* __restrict__ zs = xs + 2 * NPTS;
    float* __restrict__ ob = out + (size_t)b * 3 * NPOINT;

    const int tid = threadIdx.x;
    const int w = tid >> 5, l = tid & 31;
    const int pbase = (int)rank * PER_CTA;

    float* sx = s_dyn;
    float* sy = s_dyn + PER_CTA;
    float* sz = s_dyn + 2 * PER_CTA;

    __shared__ uint32_t s_wv[NW], s_wi[NW];
    __shared__ unsigned long long s_key[2][CLUSTER];
    __shared__ float4 s_co[2][CLUSTER];

    // ---- load coords: smem table + packed registers ----
    unsigned long long xp[NPAIR], yp[NPAIR], zp[NPAIR];
    float tmp[P];
#pragma unroll
    for (int q = 0; q < NPAIR; ++q) {
        const int g0 = pbase + (2 * q)     * T + tid;
        const int g1 = pbase + (2 * q + 1) * T + tid;
        const float ax0 = xs[g0], ax1 = xs[g1];
        const float ay0 = ys[g0], ay1 = ys[g1];
        const float az0 = zs[g0], az1 = zs[g1];
        sx[(2*q)   * T + tid] = ax0;  sx[(2*q+1) * T + tid] = ax1;
        sy[(2*q)   * T + tid] = ay0;  sy[(2*q+1) * T + tid] = ay1;
        sz[(2*q)   * T + tid] = az0;  sz[(2*q+1) * T + tid] = az1;
        asm("mov.b64 %0, {%1, %2};" : "=l"(xp[q]) : "f"(ax0), "f"(ax1));
        asm("mov.b64 %0, {%1, %2};" : "=l"(yp[q]) : "f"(ay0), "f"(ay1));
        asm("mov.b64 %0, {%1, %2};" : "=l"(zp[q]) : "f"(az0), "f"(az1));
        tmp[2*q] = 1e10f; tmp[2*q+1] = 1e10f;
    }

    float lx = __ldg(xs), ly = __ldg(ys), lz = __ldg(zs);  // idx[0] = 0
    if (rank == 0 && tid == 0) {
        ob[0] = lx; ob[NPOINT] = ly; ob[2 * NPOINT] = lz;
    }

    for (int j = 1; j < NPOINT; ++j) {
        // packed negated center (per-lane duplicate)
        unsigned long long nlx2, nly2, nlz2;
        {
            const float nx = -lx, ny = -ly, nz = -lz;
            asm("mov.b64 %0, {%1, %1};" : "=l"(nlx2) : "f"(nx));
            asm("mov.b64 %0, {%1, %1};" : "=l"(nly2) : "f"(ny));
            asm("mov.b64 %0, {%1, %1};" : "=l"(nlz2) : "f"(nz));
        }

        float bv = -1.0f;
        int   bs = 0;
#pragma unroll
        for (int q = 0; q < NPAIR; ++q) {
            unsigned long long dx, dy, dz, qx, qy, qz, s01, acc;
            asm("add.rn.f32x2 %0, %1, %2;" : "=l"(dx) : "l"(xp[q]), "l"(nlx2));
            asm("add.rn.f32x2 %0, %1, %2;" : "=l"(dy) : "l"(yp[q]), "l"(nly2));
            asm("add.rn.f32x2 %0, %1, %2;" : "=l"(dz) : "l"(zp[q]), "l"(nlz2));
            asm("mul.rn.f32x2 %0, %1, %1;" : "=l"(qx) : "l"(dx));
            asm("mul.rn.f32x2 %0, %1, %1;" : "=l"(qy) : "l"(dy));
            asm("mul.rn.f32x2 %0, %1, %1;" : "=l"(qz) : "l"(dz));
            asm("add.rn.f32x2 %0, %1, %2;" : "=l"(s01) : "l"(qx), "l"(qy));
            asm("add.rn.f32x2 %0, %1, %2;" : "=l"(acc) : "l"(s01), "l"(qz));
            float d0, d1;
            asm("mov.b64 {%0, %1}, %2;" : "=f"(d0), "=f"(d1) : "l"(acc));
            float t0 = fminf(tmp[2*q], d0);     tmp[2*q] = t0;
            if (t0 > bv) { bv = t0; bs = 2*q; }
            float t1 = fminf(tmp[2*q+1], d1);   tmp[2*q+1] = t1;
            if (t1 > bv) { bv = t1; bs = 2*q+1; }
        }
        const uint32_t idx = (uint32_t)(pbase + bs * T + tid);

        // ---- warp argmax via redux (float bits of v>=0 are u32-monotone) ----
        const uint32_t vb   = __float_as_uint(bv);
        const uint32_t vmax = __reduce_max_sync(0xffffffffu, vb);
        const uint32_t imin = __reduce_min_sync(0xffffffffu,
                                   (vb == vmax) ? idx : 0xffffffffu);
        if (l == 0) { s_wv[w] = vmax; s_wi[w] = imin; }
        __syncthreads();

        const int p = j & 1;

        if (w == 0) {
            const uint32_t v  = (l < NW) ? s_wv[l] : 0u;
            const uint32_t ii = (l < NW) ? s_wi[l] : 0xffffffffu;
            const uint32_t vm = __reduce_max_sync(0xffffffffu, v);
            const uint32_t im = __reduce_min_sync(0xffffffffu,
                                    (v == vm) ? ii : 0xffffffffu);
            // redux leaves the result in every lane: lanes 0..3 disseminate
            // to cluster CTA dst == lane, in parallel.
            if (l < CLUSTER) {
                const int li = (int)im - pbase;      // winner is in own range
                const float cx = sx[li], cy = sy[li], cz = sz[li];  // LDS bcast
                const unsigned long long key =
                    ((unsigned long long)vm << 32) | (uint32_t)(~im);
                unsigned long long xyp;
                asm("mov.b64 %0, {%1, %2};" : "=l"(xyp) : "f"(cx), "f"(cy));
                const uint32_t zb = __float_as_uint(cz);
                const uint32_t ka = smem_u32(&s_key[p][rank]);
                const uint32_t ca = smem_u32(&s_co[p][rank]);
                const int dco = (int)(ca - ka);
                uint32_t rk;
                asm volatile("mapa.shared::cluster.u32 %0, %1, %2;"
                             : "=r"(rk) : "r"(ka), "r"(l));
                asm volatile("st.shared::cluster.b64 [%0], %1;"
                             :: "r"(rk), "l"(key) : "memory");
                asm volatile("st.shared::cluster.b64 [%0], %1;"
                             :: "r"(rk + dco), "l"(xyp) : "memory");
                asm volatile("st.shared::cluster.b32 [%0+8], %1;"
                             :: "r"(rk + dco), "r"(zb) : "memory");
            }
        }

        // arrive = release (orders the shared::cluster stores), wait = acquire
        asm volatile("barrier.cluster.arrive.aligned;" ::: "memory");
        asm volatile("barrier.cluster.wait.aligned;" ::: "memory");

        // ---- every thread picks the cluster winner locally (4 slots) ----
        unsigned long long k0 = s_key[p][0], k1 = s_key[p][1];
        unsigned long long k2 = s_key[p][2], k3 = s_key[p][3];
        int c0 = 0, c2 = 2;
        if (k1 > k0) { k0 = k1; c0 = 1; }
        if (k3 > k2) { k2 = k3; c2 = 3; }
        if (k2 > k0) { k0 = k2; c0 = c2; }
        const float4 co = s_co[p][c0];
        lx = co.x; ly = co.y; lz = co.z;

        if (rank == 0 && tid == 0) {
            ob[j]              = lx;
            ob[NPOINT + j]     = ly;
            ob[2 * NPOINT + j] = lz;
        }
    }
}

extern "C" void kernel_launch(void* const* d_in, const int* in_sizes, int n_in,
                              void* d_out, int out_size)
{
    (void)in_sizes; (void)n_in; (void)out_size;
    const float* xyz_t = (const float*)d_in[1];   // points_xyz_t: (B, 3, N)
    float* out = (float*)d_out;                   // (B, 3, NPOINT)

    // 96KB dynamic smem coord table -> opt-in. Host-side attribute call:
    // nothing enqueued on the stream, capture-safe, deterministic,
    // idempotent.
    const int dyn_bytes = 3 * PER_CTA * (int)sizeof(float);   // 98304
    cudaFuncSetAttribute(fps_cluster_kernel,
                         cudaFuncAttributeMaxDynamicSharedMemorySize, dyn_bytes);

    fps_cluster_kernel<<<BATCH * CLUSTER, T, dyn_bytes>>>(xyz_t, out);
}